// round 8
// baseline (speedup 1.0000x reference)
#include <cuda_runtime.h>
#include <cuda_bf16.h>
#include <cstdint>

#define BATCH 128
#define NH    8
#define NT    256
#define HDIM  64
#define MODEL 512
#define NBH   (BATCH*NH)    // 1024
#define MTOT  (BATCH*NT)    // 32768
#define QKVN  (3*NH*HDIM)   // 1536
#define KX    1536          // extended K = 3*512

// ---------------- scratch (static __device__, no runtime allocation) -------
__device__ float g_v[(size_t)NBH*NT*HDIM];
__device__ float g_S[(size_t)NBH*NT*NT];
__device__ __nv_bfloat16 g_qe[(size_t)NBH*NT*128];   // [qh|ql] per row (scaled)
__device__ __nv_bfloat16 g_ke[(size_t)NBH*NT*128];   // [kh|kl] per row
__device__ __nv_bfloat16 g_pe[(size_t)NBH*NT*512];   // [Ph|Pl] per row
__device__ __nv_bfloat16 g_vt[(size_t)NBH*64*512];   // [Vh|Vl], V transposed
__device__ __nv_bfloat16 g_xs[(size_t)MTOT*KX];      // [Ah|Al|Ah] of x
__device__ __nv_bfloat16 g_qws[(size_t)QKVN*KX];     // [Bh|Bh|Bl] of qkv_w
__device__ __nv_bfloat16 g_pws[(size_t)MODEL*KX];    // [Bh|Bh|Bl] of proj_w
__device__ __nv_bfloat16 g_ohs[(size_t)MTOT*KX];     // [Ah|Al|Ah] of attn out

// ---------------- helpers ---------------------------------------------------
__device__ __forceinline__ uint32_t smem_u32(const void* p) {
    uint32_t a;
    asm("{ .reg .u64 t; cvta.to.shared.u64 t, %1; cvt.u32.u64 %0, t; }"
        : "=r"(a) : "l"(p));
    return a;
}
__device__ __forceinline__ void cp16(uint32_t s, const void* g) {
    asm volatile("cp.async.cg.shared.global [%0], [%1], 16;" :: "r"(s), "l"(g));
}
#define CP_COMMIT() asm volatile("cp.async.commit_group;")
#define CP_WAIT1()  asm volatile("cp.async.wait_group 1;")
#define CP_WAIT2()  asm volatile("cp.async.wait_group 2;")
__device__ __forceinline__ void ldm4(uint32_t& r0, uint32_t& r1, uint32_t& r2,
                                     uint32_t& r3, uint32_t a) {
    asm volatile("ldmatrix.sync.aligned.m8n8.x4.shared.b16 {%0,%1,%2,%3}, [%4];"
                 : "=r"(r0), "=r"(r1), "=r"(r2), "=r"(r3) : "r"(a));
}
__device__ __forceinline__ void mma16816(float* c, const uint32_t* a,
                                         uint32_t b0, uint32_t b1) {
    asm volatile(
        "mma.sync.aligned.m16n8k16.row.col.f32.bf16.bf16.f32 "
        "{%0,%1,%2,%3}, {%4,%5,%6,%7}, {%8,%9}, {%0,%1,%2,%3};"
        : "+f"(c[0]), "+f"(c[1]), "+f"(c[2]), "+f"(c[3])
        : "r"(a[0]), "r"(a[1]), "r"(a[2]), "r"(a[3]), "r"(b0), "r"(b1));
}
__device__ __forceinline__ void split1(float v, __nv_bfloat16& h, __nv_bfloat16& l) {
    h = __float2bfloat16(v);
    l = __float2bfloat16(v - __bfloat162float(h));
}

// ---------------- split kernels (vectorized x2) -----------------------------
__global__ void split_a_kernel(const float* __restrict__ s, __nv_bfloat16* d,
                               int totpairs) {
    int i = blockIdx.x * 256 + threadIdx.x;
    if (i >= totpairs) return;
    int r = i >> 8, kp = i & 255;          // 256 pairs per 512-row
    float2 v = ((const float2*)s)[i];
    __nv_bfloat16 h0, l0, h1, l1;
    split1(v.x, h0, l0); split1(v.y, h1, l1);
    __nv_bfloat162 th, tl; th.x = h0; th.y = h1; tl.x = l0; tl.y = l1;
    __nv_bfloat162* base = (__nv_bfloat162*)(d + (size_t)r * KX) + kp;
    base[0] = th; base[256] = tl; base[512] = th;
}
__global__ void split_b_kernel(const float* __restrict__ s, __nv_bfloat16* d,
                               int totpairs) {
    int i = blockIdx.x * 256 + threadIdx.x;
    if (i >= totpairs) return;
    int r = i >> 8, kp = i & 255;
    float2 v = ((const float2*)s)[i];
    __nv_bfloat16 h0, l0, h1, l1;
    split1(v.x, h0, l0); split1(v.y, h1, l1);
    __nv_bfloat162 th, tl; th.x = h0; th.y = h1; tl.x = l0; tl.y = l1;
    __nv_bfloat162* base = (__nv_bfloat162*)(d + (size_t)r * KX) + kp;
    base[0] = th; base[256] = th; base[512] = tl;
}

// ---------------- bf16 mma.sync GEMM (large, dense) -------------------------
// BM=256 BN=128 BK=32, 512 threads, warp tile 64x32, 4 stages.
#define BM 256
#define BN 128
#define BK 32
#define NSTG 4
#define ROWB 80u                          // padded row: 40 bf16 = 80B
#define STGB ((BM + BN) * ROWB)           // 30720B
#define GSMEM (NSTG * STGB)               // 122880B

template<int MODE>
__global__ __launch_bounds__(512, 1) void gemm_mma(
    const __nv_bfloat16* __restrict__ gA, const __nv_bfloat16* __restrict__ gB,
    const float* __restrict__ bias, float* __restrict__ outp)
{
    extern __shared__ char smem[];
    const uint32_t sb = smem_u32(smem);
    const int tid = threadIdx.x, wid = tid >> 5, lane = tid & 31;
    const int m0 = blockIdx.y * BM;
    const int n0 = blockIdx.x * BN;
    const int warp_m = (wid & 3) * 64;
    const int warp_n = (wid >> 2) * 32;

    auto load_stage = [&](int ks, int buf) {
        const size_t kofs = (size_t)ks * BK;
        const uint32_t abase = sb + buf * STGB;
        const uint32_t bbase = abase + BM * ROWB;
        #pragma unroll
        for (int t = 0; t < 3; t++) {
            const int idx = tid + t * 512;
            if (idx < 1024) {           // A: 256 rows x 4 chunks
                const int r = idx >> 2, c = (idx & 3) * 8;
                cp16(abase + r * ROWB + c * 2, gA + (size_t)(m0 + r) * KX + kofs + c);
            } else {                    // B: 128 rows x 4 chunks
                const int j = idx - 1024;
                const int r = j >> 2, c = (j & 3) * 8;
                cp16(bbase + r * ROWB + c * 2, gB + (size_t)(n0 + r) * KX + kofs + c);
            }
        }
    };

    const int NK = KX / BK;   // 48
    load_stage(0, 0); CP_COMMIT();
    load_stage(1, 1); CP_COMMIT();
    load_stage(2, 2); CP_COMMIT();

    float acc[4][4][4] = {};
    const int a_row = warp_m + (lane & 15);
    const int a_col = (lane >> 4) * 8;
    const int b_row = warp_n + (lane & 7) + ((lane >> 4) << 3);
    const int b_col = ((lane >> 3) & 1) * 8;

    for (int ks = 0; ks < NK; ks++) {
        CP_WAIT2();
        __syncthreads();
        const int pf = ks + NSTG - 1;
        if (pf < NK) load_stage(pf, pf % NSTG);
        CP_COMMIT();
        const int buf = ks % NSTG;
        const uint32_t abase = sb + buf * STGB;
        const uint32_t bbase = abase + BM * ROWB;
        #pragma unroll
        for (int kk = 0; kk < 2; kk++) {
            uint32_t af[4][4], bfr[2][4];
            #pragma unroll
            for (int im = 0; im < 4; im++)
                ldm4(af[im][0], af[im][1], af[im][2], af[im][3],
                     abase + (a_row + im * 16) * ROWB + (kk * 16 + a_col) * 2);
            #pragma unroll
            for (int jn = 0; jn < 2; jn++)
                ldm4(bfr[jn][0], bfr[jn][1], bfr[jn][2], bfr[jn][3],
                     bbase + (b_row + jn * 16) * ROWB + (kk * 16 + b_col) * 2);
            #pragma unroll
            for (int jn = 0; jn < 2; jn++)
                #pragma unroll
                for (int im = 0; im < 4; im++) {
                    mma16816(acc[im][jn * 2 + 0], af[im], bfr[jn][0], bfr[jn][1]);
                    mma16816(acc[im][jn * 2 + 1], af[im], bfr[jn][2], bfr[jn][3]);
                }
        }
    }

    const int mb = m0 + warp_m + (lane >> 2);
    #pragma unroll
    for (int im = 0; im < 4; im++) {
        #pragma unroll
        for (int j = 0; j < 4; j++) {
            const int col = n0 + warp_n + j * 8 + (lane & 3) * 2;
            #pragma unroll
            for (int half = 0; half < 2; half++) {
                const int m = mb + im * 16 + half * 8;
                float v0 = acc[im][j][half * 2 + 0] + bias[col];
                float v1 = acc[im][j][half * 2 + 1] + bias[col + 1];
                if (MODE == 0) {
                    const int sct = col >> 9, h = (col >> 6) & 7, d = col & 63;
                    const int bi = m >> 8, nt = m & 255;
                    if (sct == 2) {
                        float2* dp = (float2*)(g_v +
                            (((size_t)(bi * NH + h) * NT + nt) * HDIM + d));
                        *dp = make_float2(v0, v1);
                    } else {
                        if (sct == 0) { v0 *= 0.125f; v1 *= 0.125f; }
                        __nv_bfloat16 h0, l0, h1, l1;
                        split1(v0, h0, l0); split1(v1, h1, l1);
                        __nv_bfloat16* base = ((sct == 0) ? g_qe : g_ke) +
                            ((size_t)(bi * NH + h) * NT + nt) * 128 + d;
                        __nv_bfloat162 th, tl;
                        th.x = h0; th.y = h1; tl.x = l0; tl.y = l1;
                        *(__nv_bfloat162*)(base)      = th;
                        *(__nv_bfloat162*)(base + 64) = tl;
                    }
                } else {
                    *(float2*)(outp + (size_t)m * MODEL + col) = make_float2(v0, v1);
                }
            }
        }
    }
}

// ---------------- s_mma: S[bh] = q_ext @ k_ext^T  (mma.sync) ----------------
#define SROWB 80u
#define SSTGB (2u * 128 * SROWB)       // 20480B
#define SSMEM (3u * SSTGB)             // 61440B

__global__ __launch_bounds__(256, 2) void s_mma()
{
    extern __shared__ char smem[];
    const uint32_t sb = smem_u32(smem);
    const int tid = threadIdx.x, wid = tid >> 5, lane = tid & 31;
    const int bh = blockIdx.y;
    const int m0 = (blockIdx.x >> 1) * 128;
    const int n0 = (blockIdx.x & 1) * 128;
    const __nv_bfloat16* gA = g_qe + (size_t)bh * NT * 128;
    const __nv_bfloat16* gB = g_ke + (size_t)bh * NT * 128;
    const int warp_m = (wid & 3) * 32;
    const int warp_n = (wid >> 2) * 64;

    const int c0r = tid >> 2, c0c = (tid & 3) * 8;
    const int c1r = (tid + 256) >> 2, c1c = ((tid + 256) & 3) * 8;

    auto aoff = [](int s) { return (s < 4) ? s * 32 : (s - 4) * 32; };
    auto boff = [](int s) { return (s < 4) ? (s & 1) * 32 : (s - 2) * 32; };

    auto load_stage = [&](int ks, int buf) {
        const int ao = aoff(ks), bo = boff(ks);
        const uint32_t abase = sb + buf * SSTGB;
        const uint32_t bbase = abase + 128 * SROWB;
        cp16(abase + c0r * SROWB + c0c * 2, gA + (size_t)(m0 + c0r) * 128 + ao + c0c);
        cp16(abase + c1r * SROWB + c1c * 2, gA + (size_t)(m0 + c1r) * 128 + ao + c1c);
        cp16(bbase + c0r * SROWB + c0c * 2, gB + (size_t)(n0 + c0r) * 128 + bo + c0c);
        cp16(bbase + c1r * SROWB + c1c * 2, gB + (size_t)(n0 + c1r) * 128 + bo + c1c);
    };

    const int NK = 6;
    load_stage(0, 0); CP_COMMIT();
    load_stage(1, 1); CP_COMMIT();

    float acc[2][8][4] = {};
    const int a_row = warp_m + (lane & 15);
    const int a_col = (lane >> 4) * 8;
    const int b_row = warp_n + (lane & 7) + ((lane >> 4) << 3);
    const int b_col = ((lane >> 3) & 1) * 8;

    for (int ks = 0; ks < NK; ks++) {
        CP_WAIT1();
        __syncthreads();
        const int pf = ks + 2;
        if (pf < NK) load_stage(pf, pf % 3);
        CP_COMMIT();
        const int buf = ks % 3;
        const uint32_t abase = sb + buf * SSTGB;
        const uint32_t bbase = abase + 128 * SROWB;
        #pragma unroll
        for (int kk = 0; kk < 2; kk++) {
            uint32_t af[2][4], bfr[4][4];
            #pragma unroll
            for (int im = 0; im < 2; im++)
                ldm4(af[im][0], af[im][1], af[im][2], af[im][3],
                     abase + (a_row + im * 16) * SROWB + (kk * 16 + a_col) * 2);
            #pragma unroll
            for (int jn = 0; jn < 4; jn++)
                ldm4(bfr[jn][0], bfr[jn][1], bfr[jn][2], bfr[jn][3],
                     bbase + (b_row + jn * 16) * SROWB + (kk * 16 + b_col) * 2);
            #pragma unroll
            for (int jn = 0; jn < 4; jn++)
                #pragma unroll
                for (int im = 0; im < 2; im++) {
                    mma16816(acc[im][jn * 2 + 0], af[im], bfr[jn][0], bfr[jn][1]);
                    mma16816(acc[im][jn * 2 + 1], af[im], bfr[jn][2], bfr[jn][3]);
                }
        }
    }

    float* Sp = g_S + (size_t)bh * NT * NT;
    const int mb = m0 + warp_m + (lane >> 2);
    #pragma unroll
    for (int im = 0; im < 2; im++) {
        #pragma unroll
        for (int j = 0; j < 8; j++) {
            const int col = n0 + warp_n + j * 8 + (lane & 3) * 2;
            #pragma unroll
            for (int half = 0; half < 2; half++) {
                const int m = mb + im * 16 + half * 8;
                *(float2*)(Sp + (size_t)m * NT + col) =
                    make_float2(acc[im][j][half * 2], acc[im][j][half * 2 + 1]);
            }
        }
    }
}

// ---------------- vt_kernel: transpose + split V ----------------------------
__global__ __launch_bounds__(256) void vt_kernel()
{
    __shared__ float sv[128 * 65];
    const int bh = blockIdx.x, tid = threadIdx.x;
    const float* V = g_v + (size_t)bh * NT * HDIM;
    __nv_bfloat16* dst = g_vt + (size_t)bh * 64 * 512;
    for (int pass = 0; pass < 2; pass++) {
        const int kbase = pass * 128;
        for (int i = tid; i < 128 * 64; i += 256) {
            int k2 = i >> 6, n = i & 63;
            sv[k2 * 65 + n] = V[(size_t)(kbase + k2) * 64 + n];
        }
        __syncthreads();
        const int n = tid >> 2, q = tid & 3;
        for (int kk = 0; kk < 32; kk += 2) {
            const int k2 = q * 32 + kk;
            float v0 = sv[k2 * 65 + n], v1 = sv[(k2 + 1) * 65 + n];
            __nv_bfloat16 h0, l0, h1, l1;
            split1(v0, h0, l0); split1(v1, h1, l1);
            __nv_bfloat162 th, tl;
            th.x = h0; th.y = h1; tl.x = l0; tl.y = l1;
            const int k = kbase + k2;
            *(__nv_bfloat162*)(dst + (size_t)n * 512 + k)       = th;
            *(__nv_bfloat162*)(dst + (size_t)n * 512 + 256 + k) = tl;
        }
        __syncthreads();
    }
}

// ---------------- conv + bias + softmax -> split P --------------------------
__global__ __launch_bounds__(256) void conv_softmax_kernel(
    const float* __restrict__ pe_w, const float* __restrict__ pe_b,
    const float* __restrict__ rpb)
{
    __shared__ float st[16][NT];
    const int bh = blockIdx.y;
    const int h  = bh & 7;
    const int i0 = blockIdx.x * 16;
    const float* S = g_S + (size_t)bh * NT * NT;
    __nv_bfloat16* pe = g_pe + (size_t)bh * NT * 512;
    const int j = threadIdx.x;

    float win[30];
    #pragma unroll
    for (int r = 0; r < 30; r++) {
        const int g = i0 - 7 + r;
        win[r] = (g >= 0 && g < NT) ? S[(size_t)g * NT + j] : 0.f;
    }
    float w[15];
    #pragma unroll
    for (int t = 0; t < 15; t++) w[t] = pe_w[h * 15 + t];
    const float pb = pe_b[h];
    const int rj = j >> 4, cj = j & 15;

    #pragma unroll
    for (int li = 0; li < 16; li++) {
        float conv = 0.f;
        #pragma unroll
        for (int t = 0; t < 15; t++)
            conv = fmaf(win[li + t], w[t], conv);
        const int ii = i0 + li;
        const int ri = ii >> 4, ci = ii & 15;
        const int idx = (ri - rj + 15) * 31 + (ci - cj + 15);
        st[li][j] = win[li + 7] + conv + pb + __ldg(&rpb[idx * 8 + h]);
    }
    __syncthreads();

    const int warp = j >> 5, lane = j & 31;
    #pragma unroll
    for (int rr = 0; rr < 2; rr++) {
        const int li = warp * 2 + rr;
        const int ii = i0 + li;
        float vals[8];
        #pragma unroll
        for (int e = 0; e < 8; e++) vals[e] = st[li][lane + e * 32];
        float mx = vals[0];
        #pragma unroll
        for (int e = 1; e < 8; e++) mx = fmaxf(mx, vals[e]);
        #pragma unroll
        for (int o = 16; o; o >>= 1) mx = fmaxf(mx, __shfl_xor_sync(0xffffffffu, mx, o));
        float sum = 0.f;
        #pragma unroll
        for (int e = 0; e < 8; e++) { vals[e] = expf(vals[e] - mx); sum += vals[e]; }
        #pragma unroll
        for (int o = 16; o; o >>= 1) sum += __shfl_xor_sync(0xffffffffu, sum, o);
        const float inv = 1.f / sum;
        #pragma unroll
        for (int e = 0; e < 8; e++) {
            const int jj = lane + e * 32;
            float pv = vals[e] * inv;
            __nv_bfloat16 hh, ll;
            split1(pv, hh, ll);
            pe[(size_t)ii * 512 + jj]       = hh;
            pe[(size_t)ii * 512 + 256 + jj] = ll;
        }
    }
}

// ---------------- av_mma: O[bh] = P_ext @ V_ext^T ---------------------------
#define AV_ASZ (256u * SROWB)           // 20480
#define AV_STG (AV_ASZ + 64u * SROWB)   // 25600
#define AVSMEM (3u * AV_STG)            // 76800

__global__ __launch_bounds__(256, 2) void av_mma()
{
    extern __shared__ char smem[];
    const uint32_t sb = smem_u32(smem);
    const int tid = threadIdx.x, wid = tid >> 5, lane = tid & 31;
    const int bh = blockIdx.x;
    const __nv_bfloat16* gA = g_pe + (size_t)bh * NT * 512;
    const __nv_bfloat16* gB = g_vt + (size_t)bh * 64 * 512;
    const int warp_m = (wid & 3) * 64;
    const int warp_n = (wid >> 2) * 32;

    auto aoff = [](int s) { return s < 8 ? s * 32 : s < 16 ? 256 + (s - 8) * 32
                                                           : (s - 16) * 32; };
    auto boff = [](int s) { return s < 8 ? s * 32 : s < 16 ? (s - 8) * 32
                                                           : 256 + (s - 16) * 32; };

    auto load_stage = [&](int ks, int buf) {
        const int ao = aoff(ks), bo = boff(ks);
        const uint32_t abase = sb + buf * AV_STG;
        const uint32_t bbase = abase + AV_ASZ;
        #pragma unroll
        for (int t = 0; t < 5; t++) {
            const int idx = tid + t * 256;
            if (idx < 1024) {
                const int r = idx >> 2, c = (idx & 3) * 8;
                cp16(abase + r * SROWB + c * 2, gA + (size_t)r * 512 + ao + c);
            } else {
                const int jx = idx - 1024;
                const int r = jx >> 2, c = (jx & 3) * 8;
                cp16(bbase + r * SROWB + c * 2, gB + (size_t)r * 512 + bo + c);
            }
        }
    };

    const int NK = 24;
    load_stage(0, 0); CP_COMMIT();
    load_stage(1, 1); CP_COMMIT();

    float acc[4][4][4] = {};
    const int a_row = warp_m + (lane & 15);
    const int a_col = (lane >> 4) * 8;
    const int b_row = warp_n + (lane & 7) + ((lane >> 4) << 3);
    const int b_col = ((lane >> 3) & 1) * 8;

    for (int ks = 0; ks < NK; ks++) {
        CP_WAIT1();
        __syncthreads();
        const int pf = ks + 2;
        if (pf < NK) load_stage(pf, pf % 3);
        CP_COMMIT();
        const int buf = ks % 3;
        const uint32_t abase = sb + buf * AV_STG;
        const uint32_t bbase = abase + AV_ASZ;
        #pragma unroll
        for (int kk = 0; kk < 2; kk++) {
            uint32_t af[4][4], bfr[2][4];
            #pragma unroll
            for (int im = 0; im < 4; im++)
                ldm4(af[im][0], af[im][1], af[im][2], af[im][3],
                     abase + (a_row + im * 16) * SROWB + (kk * 16 + a_col) * 2);
            #pragma unroll
            for (int jn = 0; jn < 2; jn++)
                ldm4(bfr[jn][0], bfr[jn][1], bfr[jn][2], bfr[jn][3],
                     bbase + (b_row + jn * 16) * SROWB + (kk * 16 + b_col) * 2);
            #pragma unroll
            for (int jn = 0; jn < 2; jn++)
                #pragma unroll
                for (int im = 0; im < 4; im++) {
                    mma16816(acc[im][jn * 2 + 0], af[im], bfr[jn][0], bfr[jn][1]);
                    mma16816(acc[im][jn * 2 + 1], af[im], bfr[jn][2], bfr[jn][3]);
                }
        }
    }

    const int bi = bh >> 3, hh = bh & 7;
    #pragma unroll
    for (int im = 0; im < 4; im++) {
        #pragma unroll
        for (int j = 0; j < 4; j++) {
            const int col = warp_n + j * 8 + (lane & 3) * 2;   // 0..63
            #pragma unroll
            for (int half = 0; half < 2; half++) {
                const int m = warp_m + im * 16 + (lane >> 2) + half * 8;
                float v0 = acc[im][j][half * 2 + 0];
                float v1 = acc[im][j][half * 2 + 1];
                __nv_bfloat16 h0, l0, h1, l1;
                split1(v0, h0, l0); split1(v1, h1, l1);
                __nv_bfloat162 th, tl;
                th.x = h0; th.y = h1; tl.x = l0; tl.y = l1;
                __nv_bfloat16* base = g_ohs + (size_t)(bi * NT + m) * KX + hh * 64 + col;
                *(__nv_bfloat162*)(base)        = th;
                *(__nv_bfloat162*)(base + 512)  = tl;
                *(__nv_bfloat162*)(base + 1024) = th;
            }
        }
    }
}

// ---------------------------------------------------------------------------
extern "C" void kernel_launch(void* const* d_in, const int* in_sizes, int n_in,
                              void* d_out, int out_size)
{
    (void)in_sizes; (void)n_in; (void)out_size;
    const float* x      = (const float*)d_in[0];
    const float* qkv_w  = (const float*)d_in[1];
    const float* qkv_b  = (const float*)d_in[2];
    const float* pe_w   = (const float*)d_in[3];
    const float* pe_b   = (const float*)d_in[4];
    const float* rpb    = (const float*)d_in[5];
    const float* proj_w = (const float*)d_in[6];
    const float* proj_b = (const float*)d_in[7];
    float* out = (float*)d_out;

    static bool attr_done = false;
    if (!attr_done) {
        cudaFuncSetAttribute(gemm_mma<0>, cudaFuncAttributeMaxDynamicSharedMemorySize, GSMEM);
        cudaFuncSetAttribute(gemm_mma<1>, cudaFuncAttributeMaxDynamicSharedMemorySize, GSMEM);
        cudaFuncSetAttribute(s_mma, cudaFuncAttributeMaxDynamicSharedMemorySize, SSMEM);
        cudaFuncSetAttribute(av_mma, cudaFuncAttributeMaxDynamicSharedMemorySize, AVSMEM);
        attr_done = true;
    }

    __nv_bfloat16 *xs, *qws, *pws, *ohs;
    cudaGetSymbolAddress((void**)&xs,  g_xs);
    cudaGetSymbolAddress((void**)&qws, g_qws);
    cudaGetSymbolAddress((void**)&pws, g_pws);
    cudaGetSymbolAddress((void**)&ohs, g_ohs);

    split_a_kernel<<<(MTOT * MODEL / 2 + 255) / 256, 256>>>(x, xs, MTOT * MODEL / 2);
    split_b_kernel<<<(QKVN * MODEL / 2 + 255) / 256, 256>>>(qkv_w, qws, QKVN * MODEL / 2);
    split_b_kernel<<<(MODEL * MODEL / 2 + 255) / 256, 256>>>(proj_w, pws, MODEL * MODEL / 2);

    gemm_mma<0><<<dim3(QKVN / BN, MTOT / BM), 512, GSMEM>>>(xs, qws, qkv_b, nullptr);

    vt_kernel<<<NBH, 256>>>();
    s_mma<<<dim3(4, NBH), 256, SSMEM>>>();
    conv_softmax_kernel<<<dim3(16, NBH), 256>>>(pe_w, pe_b, rpb);
    av_mma<<<NBH, 256, AVSMEM>>>();

    gemm_mma<1><<<dim3(MODEL / BN, MTOT / BM), 512, GSMEM>>>(ohs, pws, proj_b, out);
}

// round 10
// speedup vs baseline: 1.1190x; 1.1190x over previous
#include <cuda_runtime.h>
#include <cuda_bf16.h>
#include <cstdint>

#define BATCH 128
#define NH    8
#define NT    256
#define HDIM  64
#define MODEL 512
#define NBH   (BATCH*NH)    // 1024
#define MTOT  (BATCH*NT)    // 32768
#define QKVN  (3*NH*HDIM)   // 1536
#define KX    1536          // extended K = 3*512

// ---------------- scratch (static __device__, no runtime allocation) -------
__device__ float g_v[(size_t)NBH*NT*HDIM];
__device__ float g_S[(size_t)NBH*NT*NT];
__device__ __nv_bfloat16 g_qe[(size_t)NBH*NT*128];   // [qh|ql] per row (scaled)
__device__ __nv_bfloat16 g_ke[(size_t)NBH*NT*128];   // [kh|kl] per row
__device__ __nv_bfloat16 g_pe[(size_t)NBH*NT*512];   // [Ph|Pl] per row
__device__ __nv_bfloat16 g_vt[(size_t)NBH*64*512];   // [Vh|Vl], V transposed
__device__ __nv_bfloat16 g_xs[(size_t)MTOT*KX];      // [Ah|Al|Ah] of x
__device__ __nv_bfloat16 g_qws[(size_t)QKVN*KX];     // [Bh|Bh|Bl] of qkv_w
__device__ __nv_bfloat16 g_pws[(size_t)MODEL*KX];    // [Bh|Bh|Bl] of proj_w
__device__ __nv_bfloat16 g_ohs[(size_t)MTOT*KX];     // [Ah|Al|Ah] of attn out

// ---------------- helpers ---------------------------------------------------
__device__ __forceinline__ uint32_t smem_u32(const void* p) {
    uint32_t a;
    asm("{ .reg .u64 t; cvta.to.shared.u64 t, %1; cvt.u32.u64 %0, t; }"
        : "=r"(a) : "l"(p));
    return a;
}
__device__ __forceinline__ void cp16(uint32_t s, const void* g) {
    asm volatile("cp.async.cg.shared.global [%0], [%1], 16;" :: "r"(s), "l"(g));
}
#define CP_COMMIT() asm volatile("cp.async.commit_group;")
#define CP_WAIT1()  asm volatile("cp.async.wait_group 1;")
__device__ __forceinline__ void ldm4(uint32_t& r0, uint32_t& r1, uint32_t& r2,
                                     uint32_t& r3, uint32_t a) {
    asm volatile("ldmatrix.sync.aligned.m8n8.x4.shared.b16 {%0,%1,%2,%3}, [%4];"
                 : "=r"(r0), "=r"(r1), "=r"(r2), "=r"(r3) : "r"(a));
}
__device__ __forceinline__ void mma16816(float* c, const uint32_t* a,
                                         uint32_t b0, uint32_t b1) {
    asm volatile(
        "mma.sync.aligned.m16n8k16.row.col.f32.bf16.bf16.f32 "
        "{%0,%1,%2,%3}, {%4,%5,%6,%7}, {%8,%9}, {%0,%1,%2,%3};"
        : "+f"(c[0]), "+f"(c[1]), "+f"(c[2]), "+f"(c[3])
        : "r"(a[0]), "r"(a[1]), "r"(a[2]), "r"(a[3]), "r"(b0), "r"(b1));
}
__device__ __forceinline__ void split1(float v, __nv_bfloat16& h, __nv_bfloat16& l) {
    h = __float2bfloat16(v);
    l = __float2bfloat16(v - __bfloat162float(h));
}

// ---------------- split kernels (vectorized x2) -----------------------------
__global__ void split_a_kernel(const float* __restrict__ s, __nv_bfloat16* d,
                               int totpairs) {
    int i = blockIdx.x * 256 + threadIdx.x;
    if (i >= totpairs) return;
    int r = i >> 8, kp = i & 255;          // 256 pairs per 512-row
    float2 v = ((const float2*)s)[i];
    __nv_bfloat16 h0, l0, h1, l1;
    split1(v.x, h0, l0); split1(v.y, h1, l1);
    __nv_bfloat162 th, tl; th.x = h0; th.y = h1; tl.x = l0; tl.y = l1;
    __nv_bfloat162* base = (__nv_bfloat162*)(d + (size_t)r * KX) + kp;
    base[0] = th; base[256] = tl; base[512] = th;
}
__global__ void split_b_kernel(const float* __restrict__ s, __nv_bfloat16* d,
                               int totpairs) {
    int i = blockIdx.x * 256 + threadIdx.x;
    if (i >= totpairs) return;
    int r = i >> 8, kp = i & 255;
    float2 v = ((const float2*)s)[i];
    __nv_bfloat16 h0, l0, h1, l1;
    split1(v.x, h0, l0); split1(v.y, h1, l1);
    __nv_bfloat162 th, tl; th.x = h0; th.y = h1; tl.x = l0; tl.y = l1;
    __nv_bfloat162* base = (__nv_bfloat162*)(d + (size_t)r * KX) + kp;
    base[0] = th; base[256] = th; base[512] = tl;
}

// ---------------- bf16 mma.sync GEMM (large, dense) -------------------------
// BM=128 BN=128 BK=64, 256 threads, warp tile 32x64, 3 stages, 2 CTAs/SM.
#define BM 128
#define BN 128
#define BK 64
#define NSTG 3
#define ROWB 144u                         // padded row: 72 bf16 = 144B
#define STGB (2u * BM * ROWB)             // 36864B
#define GSMEM (NSTG * STGB)               // 110592B

template<int MODE>
__global__ __launch_bounds__(256, 2) void gemm_mma(
    const __nv_bfloat16* __restrict__ gA, const __nv_bfloat16* __restrict__ gB,
    const float* __restrict__ bias, float* __restrict__ outp)
{
    extern __shared__ char smem[];
    const uint32_t sb = smem_u32(smem);
    const int tid = threadIdx.x, wid = tid >> 5, lane = tid & 31;
    const int m0 = blockIdx.y * BM;
    const int n0 = blockIdx.x * BN;
    const int warp_m = (wid & 3) * 32;
    const int warp_n = (wid >> 2) * 64;

    auto load_stage = [&](int ks, int buf) {
        const size_t kofs = (size_t)ks * BK;
        const uint32_t abase = sb + buf * STGB;
        const uint32_t bbase = abase + BM * ROWB;
        #pragma unroll
        for (int t = 0; t < 8; t++) {
            const int idx = tid + t * 256;
            if (idx < 1024) {           // A: 128 rows x 8 chunks
                const int r = idx >> 3, c = (idx & 7) * 8;
                cp16(abase + r * ROWB + c * 2, gA + (size_t)(m0 + r) * KX + kofs + c);
            } else {                    // B: 128 rows x 8 chunks
                const int j = idx - 1024;
                const int r = j >> 3, c = (j & 7) * 8;
                cp16(bbase + r * ROWB + c * 2, gB + (size_t)(n0 + r) * KX + kofs + c);
            }
        }
    };

    const int NK = KX / BK;   // 24
    load_stage(0, 0); CP_COMMIT();
    load_stage(1, 1); CP_COMMIT();

    float acc[2][8][4] = {};
    const int a_row = warp_m + (lane & 15);
    const int a_col = (lane >> 4) * 8;
    const int b_row = warp_n + (lane & 7) + ((lane >> 4) << 3);
    const int b_col = ((lane >> 3) & 1) * 8;

    for (int ks = 0; ks < NK; ks++) {
        CP_WAIT1();
        __syncthreads();
        const int pf = ks + NSTG - 1;
        if (pf < NK) load_stage(pf, pf % NSTG);
        CP_COMMIT();
        const int buf = ks % NSTG;
        const uint32_t abase = sb + buf * STGB;
        const uint32_t bbase = abase + BM * ROWB;
        #pragma unroll
        for (int kk = 0; kk < 4; kk++) {
            uint32_t af[2][4], bfr[4][4];
            #pragma unroll
            for (int im = 0; im < 2; im++)
                ldm4(af[im][0], af[im][1], af[im][2], af[im][3],
                     abase + (a_row + im * 16) * ROWB + (kk * 16 + a_col) * 2);
            #pragma unroll
            for (int jn = 0; jn < 4; jn++)
                ldm4(bfr[jn][0], bfr[jn][1], bfr[jn][2], bfr[jn][3],
                     bbase + (b_row + jn * 16) * ROWB + (kk * 16 + b_col) * 2);
            #pragma unroll
            for (int jn = 0; jn < 4; jn++)
                #pragma unroll
                for (int im = 0; im < 2; im++) {
                    mma16816(acc[im][jn * 2 + 0], af[im], bfr[jn][0], bfr[jn][1]);
                    mma16816(acc[im][jn * 2 + 1], af[im], bfr[jn][2], bfr[jn][3]);
                }
        }
    }

    const int mb = m0 + warp_m + (lane >> 2);
    #pragma unroll
    for (int im = 0; im < 2; im++) {
        #pragma unroll
        for (int j = 0; j < 8; j++) {
            const int col = n0 + warp_n + j * 8 + (lane & 3) * 2;
            #pragma unroll
            for (int half = 0; half < 2; half++) {
                const int m = mb + im * 16 + half * 8;
                float v0 = acc[im][j][half * 2 + 0] + bias[col];
                float v1 = acc[im][j][half * 2 + 1] + bias[col + 1];
                if (MODE == 0) {
                    const int sct = col >> 9, h = (col >> 6) & 7, d = col & 63;
                    const int bi = m >> 8, nt = m & 255;
                    if (sct == 2) {
                        float2* dp = (float2*)(g_v +
                            (((size_t)(bi * NH + h) * NT + nt) * HDIM + d));
                        *dp = make_float2(v0, v1);
                    } else {
                        if (sct == 0) { v0 *= 0.125f; v1 *= 0.125f; }
                        __nv_bfloat16 h0, l0, h1, l1;
                        split1(v0, h0, l0); split1(v1, h1, l1);
                        __nv_bfloat16* base = ((sct == 0) ? g_qe : g_ke) +
                            ((size_t)(bi * NH + h) * NT + nt) * 128 + d;
                        __nv_bfloat162 th, tl;
                        th.x = h0; th.y = h1; tl.x = l0; tl.y = l1;
                        *(__nv_bfloat162*)(base)      = th;
                        *(__nv_bfloat162*)(base + 64) = tl;
                    }
                } else {
                    *(float2*)(outp + (size_t)m * MODEL + col) = make_float2(v0, v1);
                }
            }
        }
    }
}

// ---------------- s_mma: S[bh] = q_ext @ k_ext^T  (mma.sync) ----------------
// 3 stages of K=64: (qh,kh), (ql,kh), (qh,kl)
__global__ __launch_bounds__(256, 2) void s_mma()
{
    extern __shared__ char smem[];
    const uint32_t sb = smem_u32(smem);
    const int tid = threadIdx.x, wid = tid >> 5, lane = tid & 31;
    const int bh = blockIdx.y;
    const int m0 = (blockIdx.x >> 1) * 128;
    const int n0 = (blockIdx.x & 1) * 128;
    const __nv_bfloat16* gA = g_qe + (size_t)bh * NT * 128;
    const __nv_bfloat16* gB = g_ke + (size_t)bh * NT * 128;
    const int warp_m = (wid & 3) * 32;
    const int warp_n = (wid >> 2) * 64;

    auto aoff = [](int s) { return (s == 1) ? 64 : 0; };
    auto boff = [](int s) { return (s == 2) ? 64 : 0; };

    auto load_stage = [&](int ks, int buf) {
        const int ao = aoff(ks), bo = boff(ks);
        const uint32_t abase = sb + buf * STGB;
        const uint32_t bbase = abase + BM * ROWB;
        #pragma unroll
        for (int t = 0; t < 8; t++) {
            const int idx = tid + t * 256;
            if (idx < 1024) {
                const int r = idx >> 3, c = (idx & 7) * 8;
                cp16(abase + r * ROWB + c * 2, gA + (size_t)(m0 + r) * 128 + ao + c);
            } else {
                const int j = idx - 1024;
                const int r = j >> 3, c = (j & 7) * 8;
                cp16(bbase + r * ROWB + c * 2, gB + (size_t)(n0 + r) * 128 + bo + c);
            }
        }
    };

    const int NK = 3;
    load_stage(0, 0); CP_COMMIT();
    load_stage(1, 1); CP_COMMIT();

    float acc[2][8][4] = {};
    const int a_row = warp_m + (lane & 15);
    const int a_col = (lane >> 4) * 8;
    const int b_row = warp_n + (lane & 7) + ((lane >> 4) << 3);
    const int b_col = ((lane >> 3) & 1) * 8;

    for (int ks = 0; ks < NK; ks++) {
        CP_WAIT1();
        __syncthreads();
        const int pf = ks + 2;
        if (pf < NK) load_stage(pf, pf % 3);
        CP_COMMIT();
        const int buf = ks % 3;
        const uint32_t abase = sb + buf * STGB;
        const uint32_t bbase = abase + BM * ROWB;
        #pragma unroll
        for (int kk = 0; kk < 4; kk++) {
            uint32_t af[2][4], bfr[4][4];
            #pragma unroll
            for (int im = 0; im < 2; im++)
                ldm4(af[im][0], af[im][1], af[im][2], af[im][3],
                     abase + (a_row + im * 16) * ROWB + (kk * 16 + a_col) * 2);
            #pragma unroll
            for (int jn = 0; jn < 4; jn++)
                ldm4(bfr[jn][0], bfr[jn][1], bfr[jn][2], bfr[jn][3],
                     bbase + (b_row + jn * 16) * ROWB + (kk * 16 + b_col) * 2);
            #pragma unroll
            for (int jn = 0; jn < 4; jn++)
                #pragma unroll
                for (int im = 0; im < 2; im++) {
                    mma16816(acc[im][jn * 2 + 0], af[im], bfr[jn][0], bfr[jn][1]);
                    mma16816(acc[im][jn * 2 + 1], af[im], bfr[jn][2], bfr[jn][3]);
                }
        }
    }

    float* Sp = g_S + (size_t)bh * NT * NT;
    const int mb = m0 + warp_m + (lane >> 2);
    #pragma unroll
    for (int im = 0; im < 2; im++) {
        #pragma unroll
        for (int j = 0; j < 8; j++) {
            const int col = n0 + warp_n + j * 8 + (lane & 3) * 2;
            #pragma unroll
            for (int half = 0; half < 2; half++) {
                const int m = mb + im * 16 + half * 8;
                *(float2*)(Sp + (size_t)m * NT + col) =
                    make_float2(acc[im][j][half * 2], acc[im][j][half * 2 + 1]);
            }
        }
    }
}

// ---------------- vt_kernel: transpose + split V ----------------------------
__global__ __launch_bounds__(256) void vt_kernel()
{
    __shared__ float sv[128 * 65];
    const int bh = blockIdx.x, tid = threadIdx.x;
    const float* V = g_v + (size_t)bh * NT * HDIM;
    __nv_bfloat16* dst = g_vt + (size_t)bh * 64 * 512;
    for (int pass = 0; pass < 2; pass++) {
        const int kbase = pass * 128;
        for (int i = tid; i < 128 * 64; i += 256) {
            int k2 = i >> 6, n = i & 63;
            sv[k2 * 65 + n] = V[(size_t)(kbase + k2) * 64 + n];
        }
        __syncthreads();
        const int n = tid >> 2, q = tid & 3;
        for (int kk = 0; kk < 32; kk += 2) {
            const int k2 = q * 32 + kk;
            float v0 = sv[k2 * 65 + n], v1 = sv[(k2 + 1) * 65 + n];
            __nv_bfloat16 h0, l0, h1, l1;
            split1(v0, h0, l0); split1(v1, h1, l1);
            __nv_bfloat162 th, tl;
            th.x = h0; th.y = h1; tl.x = l0; tl.y = l1;
            const int k = kbase + k2;
            *(__nv_bfloat162*)(dst + (size_t)n * 512 + k)       = th;
            *(__nv_bfloat162*)(dst + (size_t)n * 512 + 256 + k) = tl;
        }
        __syncthreads();
    }
}

// ---------------- conv + bias + softmax -> split P --------------------------
__global__ __launch_bounds__(256) void conv_softmax_kernel(
    const float* __restrict__ pe_w, const float* __restrict__ pe_b,
    const float* __restrict__ rpb)
{
    __shared__ float st[16][NT];
    const int bh = blockIdx.y;
    const int h  = bh & 7;
    const int i0 = blockIdx.x * 16;
    const float* S = g_S + (size_t)bh * NT * NT;
    __nv_bfloat16* pe = g_pe + (size_t)bh * NT * 512;
    const int j = threadIdx.x;

    float win[30];
    #pragma unroll
    for (int r = 0; r < 30; r++) {
        const int g = i0 - 7 + r;
        win[r] = (g >= 0 && g < NT) ? S[(size_t)g * NT + j] : 0.f;
    }
    float w[15];
    #pragma unroll
    for (int t = 0; t < 15; t++) w[t] = pe_w[h * 15 + t];
    const float pb = pe_b[h];
    const int rj = j >> 4, cj = j & 15;

    #pragma unroll
    for (int li = 0; li < 16; li++) {
        float conv = 0.f;
        #pragma unroll
        for (int t = 0; t < 15; t++)
            conv = fmaf(win[li + t], w[t], conv);
        const int ii = i0 + li;
        const int ri = ii >> 4, ci = ii & 15;
        const int idx = (ri - rj + 15) * 31 + (ci - cj + 15);
        st[li][j] = win[li + 7] + conv + pb + __ldg(&rpb[idx * 8 + h]);
    }
    __syncthreads();

    const int warp = j >> 5, lane = j & 31;
    #pragma unroll
    for (int rr = 0; rr < 2; rr++) {
        const int li = warp * 2 + rr;
        const int ii = i0 + li;
        float vals[8];
        #pragma unroll
        for (int e = 0; e < 8; e++) vals[e] = st[li][lane + e * 32];
        float mx = vals[0];
        #pragma unroll
        for (int e = 1; e < 8; e++) mx = fmaxf(mx, vals[e]);
        #pragma unroll
        for (int o = 16; o; o >>= 1) mx = fmaxf(mx, __shfl_xor_sync(0xffffffffu, mx, o));
        float sum = 0.f;
        #pragma unroll
        for (int e = 0; e < 8; e++) { vals[e] = expf(vals[e] - mx); sum += vals[e]; }
        #pragma unroll
        for (int o = 16; o; o >>= 1) sum += __shfl_xor_sync(0xffffffffu, sum, o);
        const float inv = 1.f / sum;
        #pragma unroll
        for (int e = 0; e < 8; e++) {
            const int jj = lane + e * 32;
            float pv = vals[e] * inv;
            __nv_bfloat16 hh, ll;
            split1(pv, hh, ll);
            pe[(size_t)ii * 512 + jj]       = hh;
            pe[(size_t)ii * 512 + 256 + jj] = ll;
        }
    }
}

// ---------------- av_mma: O[bh] = P_ext @ V_ext^T ---------------------------
#define SROWB 80u
#define AV_ASZ (256u * SROWB)           // 20480
#define AV_STG (AV_ASZ + 64u * SROWB)   // 25600
#define AVSMEM (3u * AV_STG)            // 76800

__global__ __launch_bounds__(256, 2) void av_mma()
{
    extern __shared__ char smem[];
    const uint32_t sb = smem_u32(smem);
    const int tid = threadIdx.x, wid = tid >> 5, lane = tid & 31;
    const int bh = blockIdx.x;
    const __nv_bfloat16* gA = g_pe + (size_t)bh * NT * 512;
    const __nv_bfloat16* gB = g_vt + (size_t)bh * 64 * 512;
    const int warp_m = (wid & 3) * 64;
    const int warp_n = (wid >> 2) * 32;

    auto aoff = [](int s) { return s < 8 ? s * 32 : s < 16 ? 256 + (s - 8) * 32
                                                           : (s - 16) * 32; };
    auto boff = [](int s) { return s < 8 ? s * 32 : s < 16 ? (s - 8) * 32
                                                           : 256 + (s - 16) * 32; };

    auto load_stage = [&](int ks, int buf) {
        const int ao = aoff(ks), bo = boff(ks);
        const uint32_t abase = sb + buf * AV_STG;
        const uint32_t bbase = abase + AV_ASZ;
        #pragma unroll
        for (int t = 0; t < 5; t++) {
            const int idx = tid + t * 256;
            if (idx < 1024) {
                const int r = idx >> 2, c = (idx & 3) * 8;
                cp16(abase + r * SROWB + c * 2, gA + (size_t)r * 512 + ao + c);
            } else {
                const int jx = idx - 1024;
                const int r = jx >> 2, c = (jx & 3) * 8;
                cp16(bbase + r * SROWB + c * 2, gB + (size_t)r * 512 + bo + c);
            }
        }
    };

    const int NK = 24;
    load_stage(0, 0); CP_COMMIT();
    load_stage(1, 1); CP_COMMIT();

    float acc[4][4][4] = {};
    const int a_row = warp_m + (lane & 15);
    const int a_col = (lane >> 4) * 8;
    const int b_row = warp_n + (lane & 7) + ((lane >> 4) << 3);
    const int b_col = ((lane >> 3) & 1) * 8;

    for (int ks = 0; ks < NK; ks++) {
        CP_WAIT1();
        __syncthreads();
        const int pf = ks + 2;
        if (pf < NK) load_stage(pf, pf % 3);
        CP_COMMIT();
        const int buf = ks % 3;
        const uint32_t abase = sb + buf * AV_STG;
        const uint32_t bbase = abase + AV_ASZ;
        #pragma unroll
        for (int kk = 0; kk < 2; kk++) {
            uint32_t af[4][4], bfr[2][4];
            #pragma unroll
            for (int im = 0; im < 4; im++)
                ldm4(af[im][0], af[im][1], af[im][2], af[im][3],
                     abase + (a_row + im * 16) * SROWB + (kk * 16 + a_col) * 2);
            #pragma unroll
            for (int jn = 0; jn < 2; jn++)
                ldm4(bfr[jn][0], bfr[jn][1], bfr[jn][2], bfr[jn][3],
                     bbase + (b_row + jn * 16) * SROWB + (kk * 16 + b_col) * 2);
            #pragma unroll
            for (int jn = 0; jn < 2; jn++)
                #pragma unroll
                for (int im = 0; im < 4; im++) {
                    mma16816(acc[im][jn * 2 + 0], af[im], bfr[jn][0], bfr[jn][1]);
                    mma16816(acc[im][jn * 2 + 1], af[im], bfr[jn][2], bfr[jn][3]);
                }
        }
    }

    const int bi = bh >> 3, hh = bh & 7;
    #pragma unroll
    for (int im = 0; im < 4; im++) {
        #pragma unroll
        for (int j = 0; j < 4; j++) {
            const int col = warp_n + j * 8 + (lane & 3) * 2;   // 0..63
            #pragma unroll
            for (int half = 0; half < 2; half++) {
                const int m = warp_m + im * 16 + (lane >> 2) + half * 8;
                float v0 = acc[im][j][half * 2 + 0];
                float v1 = acc[im][j][half * 2 + 1];
                __nv_bfloat16 h0, l0, h1, l1;
                split1(v0, h0, l0); split1(v1, h1, l1);
                __nv_bfloat162 th, tl;
                th.x = h0; th.y = h1; tl.x = l0; tl.y = l1;
                __nv_bfloat16* base = g_ohs + (size_t)(bi * NT + m) * KX + hh * 64 + col;
                *(__nv_bfloat162*)(base)        = th;
                *(__nv_bfloat162*)(base + 512)  = tl;
                *(__nv_bfloat162*)(base + 1024) = th;
            }
        }
    }
}

// ---------------------------------------------------------------------------
extern "C" void kernel_launch(void* const* d_in, const int* in_sizes, int n_in,
                              void* d_out, int out_size)
{
    (void)in_sizes; (void)n_in; (void)out_size;
    const float* x      = (const float*)d_in[0];
    const float* qkv_w  = (const float*)d_in[1];
    const float* qkv_b  = (const float*)d_in[2];
    const float* pe_w   = (const float*)d_in[3];
    const float* pe_b   = (const float*)d_in[4];
    const float* rpb    = (const float*)d_in[5];
    const float* proj_w = (const float*)d_in[6];
    const float* proj_b = (const float*)d_in[7];
    float* out = (float*)d_out;

    static bool attr_done = false;
    if (!attr_done) {
        cudaFuncSetAttribute(gemm_mma<0>, cudaFuncAttributeMaxDynamicSharedMemorySize, GSMEM);
        cudaFuncSetAttribute(gemm_mma<1>, cudaFuncAttributeMaxDynamicSharedMemorySize, GSMEM);
        cudaFuncSetAttribute(s_mma, cudaFuncAttributeMaxDynamicSharedMemorySize, GSMEM);
        cudaFuncSetAttribute(av_mma, cudaFuncAttributeMaxDynamicSharedMemorySize, AVSMEM);
        attr_done = true;
    }

    __nv_bfloat16 *xs, *qws, *pws, *ohs;
    cudaGetSymbolAddress((void**)&xs,  g_xs);
    cudaGetSymbolAddress((void**)&qws, g_qws);
    cudaGetSymbolAddress((void**)&pws, g_pws);
    cudaGetSymbolAddress((void**)&ohs, g_ohs);

    split_a_kernel<<<(MTOT * MODEL / 2 + 255) / 256, 256>>>(x, xs, MTOT * MODEL / 2);
    split_b_kernel<<<(QKVN * MODEL / 2 + 255) / 256, 256>>>(qkv_w, qws, QKVN * MODEL / 2);
    split_b_kernel<<<(MODEL * MODEL / 2 + 255) / 256, 256>>>(proj_w, pws, MODEL * MODEL / 2);

    gemm_mma<0><<<dim3(QKVN / BN, MTOT / BM), 256, GSMEM>>>(xs, qws, qkv_b, nullptr);

    vt_kernel<<<NBH, 256>>>();
    s_mma<<<dim3(4, NBH), 256, GSMEM>>>();
    conv_softmax_kernel<<<dim3(16, NBH), 256>>>(pe_w, pe_b, rpb);
    av_mma<<<NBH, 256, AVSMEM>>>();

    gemm_mma<1><<<dim3(MODEL / BN, MTOT / BM), 256, GSMEM>>>(ohs, pws, proj_b, out);
}

// round 11
// speedup vs baseline: 1.1223x; 1.0029x over previous
#include <cuda_runtime.h>
#include <cuda_bf16.h>
#include <cstdint>

#define BATCH 128
#define NH    8
#define NT    256
#define HDIM  64
#define MODEL 512
#define NBH   (BATCH*NH)    // 1024
#define MTOT  (BATCH*NT)    // 32768
#define QKVN  (3*NH*HDIM)   // 1536
#define KX    1536          // extended K = 3*512

// ---------------- scratch (static __device__, no runtime allocation) -------
__device__ float g_v[(size_t)NBH*NT*HDIM];
__device__ float g_S[(size_t)NBH*NT*NT];
__device__ __nv_bfloat16 g_qe[(size_t)NBH*NT*128];   // [qh|ql] per row (scaled)
__device__ __nv_bfloat16 g_ke[(size_t)NBH*NT*128];   // [kh|kl] per row
__device__ __nv_bfloat16 g_pe[(size_t)NBH*NT*512];   // [Ph|Pl] per row
__device__ __nv_bfloat16 g_vt[(size_t)NBH*64*512];   // [Vh|Vl], V transposed
__device__ __nv_bfloat16 g_xs[(size_t)MTOT*KX];      // [Ah|Al|Ah] of x
__device__ __nv_bfloat16 g_qws[(size_t)QKVN*KX];     // [Bh|Bh|Bl] of qkv_w
__device__ __nv_bfloat16 g_pws[(size_t)MODEL*KX];    // [Bh|Bh|Bl] of proj_w
__device__ __nv_bfloat16 g_ohs[(size_t)MTOT*KX];     // [Ah|Al|Ah] of attn out

// ---------------- helpers ---------------------------------------------------
__device__ __forceinline__ uint32_t smem_u32(const void* p) {
    uint32_t a;
    asm("{ .reg .u64 t; cvta.to.shared.u64 t, %1; cvt.u32.u64 %0, t; }"
        : "=r"(a) : "l"(p));
    return a;
}
__device__ __forceinline__ void cp16(uint32_t s, const void* g) {
    asm volatile("cp.async.cg.shared.global [%0], [%1], 16;" :: "r"(s), "l"(g));
}
#define CP_COMMIT() asm volatile("cp.async.commit_group;")
#define CP_WAIT0()  asm volatile("cp.async.wait_group 0;")
#define CP_WAIT1()  asm volatile("cp.async.wait_group 1;")
__device__ __forceinline__ void ldm4(uint32_t& r0, uint32_t& r1, uint32_t& r2,
                                     uint32_t& r3, uint32_t a) {
    asm volatile("ldmatrix.sync.aligned.m8n8.x4.shared.b16 {%0,%1,%2,%3}, [%4];"
                 : "=r"(r0), "=r"(r1), "=r"(r2), "=r"(r3) : "r"(a));
}
__device__ __forceinline__ void mma16816(float* c, const uint32_t* a,
                                         uint32_t b0, uint32_t b1) {
    asm volatile(
        "mma.sync.aligned.m16n8k16.row.col.f32.bf16.bf16.f32 "
        "{%0,%1,%2,%3}, {%4,%5,%6,%7}, {%8,%9}, {%0,%1,%2,%3};"
        : "+f"(c[0]), "+f"(c[1]), "+f"(c[2]), "+f"(c[3])
        : "r"(a[0]), "r"(a[1]), "r"(a[2]), "r"(a[3]), "r"(b0), "r"(b1));
}
__device__ __forceinline__ void split1(float v, __nv_bfloat16& h, __nv_bfloat16& l) {
    h = __float2bfloat16(v);
    l = __float2bfloat16(v - __bfloat162float(h));
}

// ---------------- split kernels (vectorized x2) -----------------------------
__global__ void split_a_kernel(const float* __restrict__ s, __nv_bfloat16* d,
                               int totpairs) {
    int i = blockIdx.x * 256 + threadIdx.x;
    if (i >= totpairs) return;
    int r = i >> 8, kp = i & 255;          // 256 pairs per 512-row
    float2 v = ((const float2*)s)[i];
    __nv_bfloat16 h0, l0, h1, l1;
    split1(v.x, h0, l0); split1(v.y, h1, l1);
    __nv_bfloat162 th, tl; th.x = h0; th.y = h1; tl.x = l0; tl.y = l1;
    __nv_bfloat162* base = (__nv_bfloat162*)(d + (size_t)r * KX) + kp;
    base[0] = th; base[256] = tl; base[512] = th;
}
__global__ void split_b_kernel(const float* __restrict__ s, __nv_bfloat16* d,
                               int totpairs) {
    int i = blockIdx.x * 256 + threadIdx.x;
    if (i >= totpairs) return;
    int r = i >> 8, kp = i & 255;
    float2 v = ((const float2*)s)[i];
    __nv_bfloat16 h0, l0, h1, l1;
    split1(v.x, h0, l0); split1(v.y, h1, l1);
    __nv_bfloat162 th, tl; th.x = h0; th.y = h1; tl.x = l0; tl.y = l1;
    __nv_bfloat162* base = (__nv_bfloat162*)(d + (size_t)r * KX) + kp;
    base[0] = th; base[256] = th; base[512] = tl;
}

// ---------------- bf16 mma.sync GEMM (large, dense) -------------------------
// BM=128 BN=128 BK=64, 256 threads, warp tile 32x64, 3 stages, 2 CTAs/SM.
#define BM 128
#define BN 128
#define BK 64
#define NSTG 3
#define ROWB 144u                         // padded row: 72 bf16 = 144B
#define STGB (2u * BM * ROWB)             // 36864B
#define GSMEM (NSTG * STGB)               // 110592B

template<int MODE>
__global__ __launch_bounds__(256, 2) void gemm_mma(
    const __nv_bfloat16* __restrict__ gA, const __nv_bfloat16* __restrict__ gB,
    const float* __restrict__ bias, float* __restrict__ outp)
{
    extern __shared__ char smem[];
    const uint32_t sb = smem_u32(smem);
    const int tid = threadIdx.x, wid = tid >> 5, lane = tid & 31;
    const int m0 = blockIdx.y * BM;
    const int n0 = blockIdx.x * BN;
    const int warp_m = (wid & 3) * 32;
    const int warp_n = (wid >> 2) * 64;

    auto load_stage = [&](int ks, int buf) {
        const size_t kofs = (size_t)ks * BK;
        const uint32_t abase = sb + buf * STGB;
        const uint32_t bbase = abase + BM * ROWB;
        #pragma unroll
        for (int t = 0; t < 8; t++) {
            const int idx = tid + t * 256;
            if (idx < 1024) {           // A: 128 rows x 8 chunks
                const int r = idx >> 3, c = (idx & 7) * 8;
                cp16(abase + r * ROWB + c * 2, gA + (size_t)(m0 + r) * KX + kofs + c);
            } else {                    // B: 128 rows x 8 chunks
                const int j = idx - 1024;
                const int r = j >> 3, c = (j & 7) * 8;
                cp16(bbase + r * ROWB + c * 2, gB + (size_t)(n0 + r) * KX + kofs + c);
            }
        }
    };

    const int NK = KX / BK;   // 24
    load_stage(0, 0); CP_COMMIT();
    load_stage(1, 1); CP_COMMIT();

    float acc[2][8][4] = {};
    const int a_row = warp_m + (lane & 15);
    const int a_col = (lane >> 4) * 8;
    const int b_row = warp_n + (lane & 7) + ((lane >> 4) << 3);
    const int b_col = ((lane >> 3) & 1) * 8;

    for (int ks = 0; ks < NK; ks++) {
        CP_WAIT1();
        __syncthreads();
        const int pf = ks + NSTG - 1;
        if (pf < NK) load_stage(pf, pf % NSTG);
        CP_COMMIT();
        const int buf = ks % NSTG;
        const uint32_t abase = sb + buf * STGB;
        const uint32_t bbase = abase + BM * ROWB;
        #pragma unroll
        for (int kk = 0; kk < 4; kk++) {
            uint32_t af[2][4], bfr[4][4];
            #pragma unroll
            for (int im = 0; im < 2; im++)
                ldm4(af[im][0], af[im][1], af[im][2], af[im][3],
                     abase + (a_row + im * 16) * ROWB + (kk * 16 + a_col) * 2);
            #pragma unroll
            for (int jn = 0; jn < 4; jn++)
                ldm4(bfr[jn][0], bfr[jn][1], bfr[jn][2], bfr[jn][3],
                     bbase + (b_row + jn * 16) * ROWB + (kk * 16 + b_col) * 2);
            #pragma unroll
            for (int jn = 0; jn < 4; jn++)
                #pragma unroll
                for (int im = 0; im < 2; im++) {
                    mma16816(acc[im][jn * 2 + 0], af[im], bfr[jn][0], bfr[jn][1]);
                    mma16816(acc[im][jn * 2 + 1], af[im], bfr[jn][2], bfr[jn][3]);
                }
        }
    }

    const int mb = m0 + warp_m + (lane >> 2);
    #pragma unroll
    for (int im = 0; im < 2; im++) {
        #pragma unroll
        for (int j = 0; j < 8; j++) {
            const int col = n0 + warp_n + j * 8 + (lane & 3) * 2;
            #pragma unroll
            for (int half = 0; half < 2; half++) {
                const int m = mb + im * 16 + half * 8;
                float v0 = acc[im][j][half * 2 + 0] + bias[col];
                float v1 = acc[im][j][half * 2 + 1] + bias[col + 1];
                if (MODE == 0) {
                    const int sct = col >> 9, h = (col >> 6) & 7, d = col & 63;
                    const int bi = m >> 8, nt = m & 255;
                    if (sct == 2) {
                        float2* dp = (float2*)(g_v +
                            (((size_t)(bi * NH + h) * NT + nt) * HDIM + d));
                        *dp = make_float2(v0, v1);
                    } else {
                        if (sct == 0) { v0 *= 0.125f; v1 *= 0.125f; }
                        __nv_bfloat16 h0, l0, h1, l1;
                        split1(v0, h0, l0); split1(v1, h1, l1);
                        __nv_bfloat16* base = ((sct == 0) ? g_qe : g_ke) +
                            ((size_t)(bi * NH + h) * NT + nt) * 128 + d;
                        __nv_bfloat162 th, tl;
                        th.x = h0; th.y = h1; tl.x = l0; tl.y = l1;
                        *(__nv_bfloat162*)(base)      = th;
                        *(__nv_bfloat162*)(base + 64) = tl;
                    }
                } else {
                    *(float2*)(outp + (size_t)m * MODEL + col) = make_float2(v0, v1);
                }
            }
        }
    }
}

// ---------------- s_mma: load-once, 3 term sweeps ---------------------------
// A = qe[m0:m0+128][0:128]  (qh|ql), B = ke[n0:n0+128][0:128] (kh|kl)
#define SROW2 272u                       // 128 elems = 256B + 16B pad
#define SSMEM2 (2u * 128u * SROW2)       // 69632B

__global__ __launch_bounds__(256, 2) void s_mma()
{
    extern __shared__ char smem[];
    const uint32_t sb = smem_u32(smem);
    const int tid = threadIdx.x, wid = tid >> 5, lane = tid & 31;
    const int bh = blockIdx.y;
    const int m0 = (blockIdx.x >> 1) * 128;
    const int n0 = (blockIdx.x & 1) * 128;
    const __nv_bfloat16* gA = g_qe + (size_t)bh * NT * 128;
    const __nv_bfloat16* gB = g_ke + (size_t)bh * NT * 128;
    const int warp_m = (wid & 3) * 32;
    const int warp_n = (wid >> 2) * 64;
    const uint32_t abase = sb;
    const uint32_t bbase = sb + 128u * SROW2;

    // load everything once: 4096 16B chunks
    #pragma unroll
    for (int t = 0; t < 16; t++) {
        const int idx = tid + t * 256;
        if (idx < 2048) {
            const int r = idx >> 4, cc = idx & 15;
            cp16(abase + r * SROW2 + cc * 16, gA + (size_t)(m0 + r) * 128 + cc * 8);
        } else {
            const int j = idx - 2048;
            const int r = j >> 4, cc = j & 15;
            cp16(bbase + r * SROW2 + cc * 16, gB + (size_t)(n0 + r) * 128 + cc * 8);
        }
    }
    CP_COMMIT();
    CP_WAIT0();
    __syncthreads();

    float acc[2][8][4] = {};
    const int a_row = warp_m + (lane & 15);
    const int a_col = (lane >> 4) * 8;
    const int b_row = warp_n + (lane & 7) + ((lane >> 4) << 3);
    const int b_col = ((lane >> 3) & 1) * 8;

    #pragma unroll
    for (int term = 0; term < 3; term++) {
        const int ao = (term == 1) ? 64 : 0;
        const int bo = (term == 2) ? 64 : 0;
        #pragma unroll
        for (int kk = 0; kk < 4; kk++) {
            uint32_t af[2][4], bfr[4][4];
            #pragma unroll
            for (int im = 0; im < 2; im++)
                ldm4(af[im][0], af[im][1], af[im][2], af[im][3],
                     abase + (a_row + im * 16) * SROW2 + (ao + kk * 16 + a_col) * 2);
            #pragma unroll
            for (int jn = 0; jn < 4; jn++)
                ldm4(bfr[jn][0], bfr[jn][1], bfr[jn][2], bfr[jn][3],
                     bbase + (b_row + jn * 16) * SROW2 + (bo + kk * 16 + b_col) * 2);
            #pragma unroll
            for (int jn = 0; jn < 4; jn++)
                #pragma unroll
                for (int im = 0; im < 2; im++) {
                    mma16816(acc[im][jn * 2 + 0], af[im], bfr[jn][0], bfr[jn][1]);
                    mma16816(acc[im][jn * 2 + 1], af[im], bfr[jn][2], bfr[jn][3]);
                }
        }
    }

    float* Sp = g_S + (size_t)bh * NT * NT;
    const int mb = m0 + warp_m + (lane >> 2);
    #pragma unroll
    for (int im = 0; im < 2; im++) {
        #pragma unroll
        for (int j = 0; j < 8; j++) {
            const int col = n0 + warp_n + j * 8 + (lane & 3) * 2;
            #pragma unroll
            for (int half = 0; half < 2; half++) {
                const int m = mb + im * 16 + half * 8;
                *(float2*)(Sp + (size_t)m * NT + col) =
                    make_float2(acc[im][j][half * 2], acc[im][j][half * 2 + 1]);
            }
        }
    }
}

// ---------------- vt_kernel: transpose + split V ----------------------------
__global__ __launch_bounds__(256) void vt_kernel()
{
    __shared__ float sv[128 * 65];
    const int bh = blockIdx.x, tid = threadIdx.x;
    const float* V = g_v + (size_t)bh * NT * HDIM;
    __nv_bfloat16* dst = g_vt + (size_t)bh * 64 * 512;
    for (int pass = 0; pass < 2; pass++) {
        const int kbase = pass * 128;
        for (int i = tid; i < 128 * 64; i += 256) {
            int k2 = i >> 6, n = i & 63;
            sv[k2 * 65 + n] = V[(size_t)(kbase + k2) * 64 + n];
        }
        __syncthreads();
        const int n = tid >> 2, q = tid & 3;
        for (int kk = 0; kk < 32; kk += 2) {
            const int k2 = q * 32 + kk;
            float v0 = sv[k2 * 65 + n], v1 = sv[(k2 + 1) * 65 + n];
            __nv_bfloat16 h0, l0, h1, l1;
            split1(v0, h0, l0); split1(v1, h1, l1);
            __nv_bfloat162 th, tl;
            th.x = h0; th.y = h1; tl.x = l0; tl.y = l1;
            const int k = kbase + k2;
            *(__nv_bfloat162*)(dst + (size_t)n * 512 + k)       = th;
            *(__nv_bfloat162*)(dst + (size_t)n * 512 + 256 + k) = tl;
        }
        __syncthreads();
    }
}

// ---------------- conv + bias + softmax -> split P (32-row chunks) ----------
__global__ __launch_bounds__(256) void conv_softmax_kernel(
    const float* __restrict__ pe_w, const float* __restrict__ pe_b,
    const float* __restrict__ rpb)
{
    __shared__ float st[32][NT];
    const int bh = blockIdx.y;
    const int h  = bh & 7;
    const int i0 = blockIdx.x * 32;
    const float* S = g_S + (size_t)bh * NT * NT;
    __nv_bfloat16* pe = g_pe + (size_t)bh * NT * 512;
    const int j = threadIdx.x;

    float win[46];
    #pragma unroll
    for (int r = 0; r < 46; r++) {
        const int g = i0 - 7 + r;
        win[r] = (g >= 0 && g < NT) ? S[(size_t)g * NT + j] : 0.f;
    }
    float w[15];
    #pragma unroll
    for (int t = 0; t < 15; t++) w[t] = pe_w[h * 15 + t];
    const float pb = pe_b[h];
    const int rj = j >> 4, cj = j & 15;

    #pragma unroll
    for (int li = 0; li < 32; li++) {
        float conv = 0.f;
        #pragma unroll
        for (int t = 0; t < 15; t++)
            conv = fmaf(win[li + t], w[t], conv);
        const int ii = i0 + li;
        const int ri = ii >> 4, ci = ii & 15;
        const int idx = (ri - rj + 15) * 31 + (ci - cj + 15);
        st[li][j] = win[li + 7] + conv + pb + __ldg(&rpb[idx * 8 + h]);
    }
    __syncthreads();

    const int warp = j >> 5, lane = j & 31;
    #pragma unroll
    for (int rr = 0; rr < 4; rr++) {
        const int li = warp * 4 + rr;
        const int ii = i0 + li;
        float vals[8];
        #pragma unroll
        for (int e = 0; e < 8; e++) vals[e] = st[li][lane + e * 32];
        float mx = vals[0];
        #pragma unroll
        for (int e = 1; e < 8; e++) mx = fmaxf(mx, vals[e]);
        #pragma unroll
        for (int o = 16; o; o >>= 1) mx = fmaxf(mx, __shfl_xor_sync(0xffffffffu, mx, o));
        float sum = 0.f;
        #pragma unroll
        for (int e = 0; e < 8; e++) { vals[e] = expf(vals[e] - mx); sum += vals[e]; }
        #pragma unroll
        for (int o = 16; o; o >>= 1) sum += __shfl_xor_sync(0xffffffffu, sum, o);
        const float inv = 1.f / sum;
        #pragma unroll
        for (int e = 0; e < 8; e++) {
            const int jj = lane + e * 32;
            float pv = vals[e] * inv;
            __nv_bfloat16 hh, ll;
            split1(pv, hh, ll);
            pe[(size_t)ii * 512 + jj]       = hh;
            pe[(size_t)ii * 512 + 256 + jj] = ll;
        }
    }
}

// ---------------- av_mma: O[bh] = P_ext @ V_ext^T (load-once chunks) --------
// per 32-wide K-chunk: load Ph, Pl (256x32 each), Vh, Vl (64x32 each) once;
// mma sweeps Ph*Vh, Ph*Vl, Pl*Vh reuse the A fragment for the first two.
#define AVROW 80u
#define AV_PH 0u
#define AV_PL (256u * AVROW)             // 20480
#define AV_VH (2u * 256u * AVROW)        // 40960
#define AV_VL (AV_VH + 64u * AVROW)      // 46080
#define AV_STG2 (AV_VL + 64u * AVROW)    // 51200
#define AVSMEM2 (2u * AV_STG2)           // 102400

__global__ __launch_bounds__(256, 2) void av_mma()
{
    extern __shared__ char smem[];
    const uint32_t sb = smem_u32(smem);
    const int tid = threadIdx.x, wid = tid >> 5, lane = tid & 31;
    const int bh = blockIdx.x;
    const __nv_bfloat16* gA = g_pe + (size_t)bh * NT * 512;
    const __nv_bfloat16* gB = g_vt + (size_t)bh * 64 * 512;
    const int warp_m = (wid & 3) * 64;
    const int warp_n = (wid >> 2) * 32;

    auto load_stage = [&](int c, int buf) {
        const uint32_t base = sb + buf * AV_STG2;
        #pragma unroll
        for (int t = 0; t < 10; t++) {
            const int idx = tid + t * 256;
            if (idx < 1024) {                     // Ph: 256 rows x 4 chunks
                const int r = idx >> 2, col = (idx & 3) * 8;
                cp16(base + AV_PH + r * AVROW + col * 2,
                     gA + (size_t)r * 512 + c * 32 + col);
            } else if (idx < 2048) {              // Pl
                const int i2 = idx - 1024;
                const int r = i2 >> 2, col = (i2 & 3) * 8;
                cp16(base + AV_PL + r * AVROW + col * 2,
                     gA + (size_t)r * 512 + 256 + c * 32 + col);
            } else if (idx < 2304) {              // Vh: 64 rows x 4 chunks
                const int i3 = idx - 2048;
                const int r = i3 >> 2, col = (i3 & 3) * 8;
                cp16(base + AV_VH + r * AVROW + col * 2,
                     gB + (size_t)r * 512 + c * 32 + col);
            } else {                              // Vl
                const int i4 = idx - 2304;
                const int r = i4 >> 2, col = (i4 & 3) * 8;
                cp16(base + AV_VL + r * AVROW + col * 2,
                     gB + (size_t)r * 512 + 256 + c * 32 + col);
            }
        }
    };

    load_stage(0, 0); CP_COMMIT();

    float acc[4][4][4] = {};
    const int a_row = warp_m + (lane & 15);
    const int a_col = (lane >> 4) * 8;
    const int b_row = warp_n + (lane & 7) + ((lane >> 4) << 3);
    const int b_col = ((lane >> 3) & 1) * 8;

    for (int ks = 0; ks < 8; ks++) {
        if (ks > 0) __syncthreads();          // protect buffer overwrite
        if (ks + 1 < 8) load_stage(ks + 1, (ks + 1) & 1);
        CP_COMMIT();
        if (ks < 7) CP_WAIT1(); else CP_WAIT0();
        __syncthreads();
        const uint32_t base = sb + (ks & 1) * AV_STG2;
        #pragma unroll
        for (int kk = 0; kk < 2; kk++) {
            uint32_t af[4][4], bh2[2][4], bl2[2][4];
            #pragma unroll
            for (int im = 0; im < 4; im++)
                ldm4(af[im][0], af[im][1], af[im][2], af[im][3],
                     base + AV_PH + (a_row + im * 16) * AVROW + (kk * 16 + a_col) * 2);
            #pragma unroll
            for (int jn = 0; jn < 2; jn++) {
                ldm4(bh2[jn][0], bh2[jn][1], bh2[jn][2], bh2[jn][3],
                     base + AV_VH + (b_row + jn * 16) * AVROW + (kk * 16 + b_col) * 2);
                ldm4(bl2[jn][0], bl2[jn][1], bl2[jn][2], bl2[jn][3],
                     base + AV_VL + (b_row + jn * 16) * AVROW + (kk * 16 + b_col) * 2);
            }
            #pragma unroll
            for (int jn = 0; jn < 2; jn++)
                #pragma unroll
                for (int im = 0; im < 4; im++) {
                    mma16816(acc[im][jn * 2 + 0], af[im], bh2[jn][0], bh2[jn][1]);
                    mma16816(acc[im][jn * 2 + 1], af[im], bh2[jn][2], bh2[jn][3]);
                    mma16816(acc[im][jn * 2 + 0], af[im], bl2[jn][0], bl2[jn][1]);
                    mma16816(acc[im][jn * 2 + 1], af[im], bl2[jn][2], bl2[jn][3]);
                }
            #pragma unroll
            for (int im = 0; im < 4; im++)
                ldm4(af[im][0], af[im][1], af[im][2], af[im][3],
                     base + AV_PL + (a_row + im * 16) * AVROW + (kk * 16 + a_col) * 2);
            #pragma unroll
            for (int jn = 0; jn < 2; jn++)
                #pragma unroll
                for (int im = 0; im < 4; im++) {
                    mma16816(acc[im][jn * 2 + 0], af[im], bh2[jn][0], bh2[jn][1]);
                    mma16816(acc[im][jn * 2 + 1], af[im], bh2[jn][2], bh2[jn][3]);
                }
        }
    }

    const int bi = bh >> 3, hh = bh & 7;
    #pragma unroll
    for (int im = 0; im < 4; im++) {
        #pragma unroll
        for (int j = 0; j < 4; j++) {
            const int col = warp_n + j * 8 + (lane & 3) * 2;   // 0..63
            #pragma unroll
            for (int half = 0; half < 2; half++) {
                const int m = warp_m + im * 16 + (lane >> 2) + half * 8;
                float v0 = acc[im][j][half * 2 + 0];
                float v1 = acc[im][j][half * 2 + 1];
                __nv_bfloat16 h0, l0, h1, l1;
                split1(v0, h0, l0); split1(v1, h1, l1);
                __nv_bfloat162 th, tl;
                th.x = h0; th.y = h1; tl.x = l0; tl.y = l1;
                __nv_bfloat16* base = g_ohs + (size_t)(bi * NT + m) * KX + hh * 64 + col;
                *(__nv_bfloat162*)(base)        = th;
                *(__nv_bfloat162*)(base + 512)  = tl;
                *(__nv_bfloat162*)(base + 1024) = th;
            }
        }
    }
}

// ---------------------------------------------------------------------------
extern "C" void kernel_launch(void* const* d_in, const int* in_sizes, int n_in,
                              void* d_out, int out_size)
{
    (void)in_sizes; (void)n_in; (void)out_size;
    const float* x      = (const float*)d_in[0];
    const float* qkv_w  = (const float*)d_in[1];
    const float* qkv_b  = (const float*)d_in[2];
    const float* pe_w   = (const float*)d_in[3];
    const float* pe_b   = (const float*)d_in[4];
    const float* rpb    = (const float*)d_in[5];
    const float* proj_w = (const float*)d_in[6];
    const float* proj_b = (const float*)d_in[7];
    float* out = (float*)d_out;

    static bool attr_done = false;
    if (!attr_done) {
        cudaFuncSetAttribute(gemm_mma<0>, cudaFuncAttributeMaxDynamicSharedMemorySize, GSMEM);
        cudaFuncSetAttribute(gemm_mma<1>, cudaFuncAttributeMaxDynamicSharedMemorySize, GSMEM);
        cudaFuncSetAttribute(s_mma, cudaFuncAttributeMaxDynamicSharedMemorySize, SSMEM2);
        cudaFuncSetAttribute(av_mma, cudaFuncAttributeMaxDynamicSharedMemorySize, AVSMEM2);
        attr_done = true;
    }

    __nv_bfloat16 *xs, *qws, *pws, *ohs;
    cudaGetSymbolAddress((void**)&xs,  g_xs);
    cudaGetSymbolAddress((void**)&qws, g_qws);
    cudaGetSymbolAddress((void**)&pws, g_pws);
    cudaGetSymbolAddress((void**)&ohs, g_ohs);

    split_a_kernel<<<(MTOT * MODEL / 2 + 255) / 256, 256>>>(x, xs, MTOT * MODEL / 2);
    split_b_kernel<<<(QKVN * MODEL / 2 + 255) / 256, 256>>>(qkv_w, qws, QKVN * MODEL / 2);
    split_b_kernel<<<(MODEL * MODEL / 2 + 255) / 256, 256>>>(proj_w, pws, MODEL * MODEL / 2);

    gemm_mma<0><<<dim3(QKVN / BN, MTOT / BM), 256, GSMEM>>>(xs, qws, qkv_b, nullptr);

    vt_kernel<<<NBH, 256>>>();
    s_mma<<<dim3(4, NBH), 256, SSMEM2>>>();
    conv_softmax_kernel<<<dim3(8, NBH), 256>>>(pe_w, pe_b, rpb);
    av_mma<<<NBH, 256, AVSMEM2>>>();

    gemm_mma<1><<<dim3(MODEL / BN, MTOT / BM), 256, GSMEM>>>(ohs, pws, proj_b, out);
}